// round 1
// baseline (speedup 1.0000x reference)
#include <cuda_runtime.h>

// ---------------------------------------------------------------------------
// Fused: conv1(1->32,3x3,valid,relu) -> conv2(32->3,3x3,valid) -> SIFT128 per
// channel-patch -> L2 norm -> pow 0.9 -> 384x10 linear -> relu -> softmax.
// One CTA per image, 256 threads, everything resident in shared memory.
// ---------------------------------------------------------------------------

__constant__ float c_w1[288];   // [32][3][3]
__constant__ float c_b1[32];
__constant__ float c_w2[864];   // [3][32][3][3]  (OIHW)
__constant__ float c_b2[3];
__constant__ float c_bl[10];

// shared memory layout (floats)
#define SM_XS      0                  // 28 rows, stride 29  -> 812
#define SM_A1      812                // 32 ch, 26 rows, stride 28 -> 23296
#define SM_A2P     (SM_A1 + 23296)    // 3 ch, padded 26x26 -> 2028
#define SM_CELLS   (SM_A2P + 2028)    // 3*128 = 384
#define SM_NORMS   (SM_CELLS + 384)   // 4
#define SM_LOGITS  (SM_NORMS + 4)     // 12
#define SM_FLOATS  (SM_LOGITS + 12)   // 26536 floats = 106144 bytes

__global__ __launch_bounds__(256, 2)
void fused_sift_net(const float* __restrict__ x,
                    const float* __restrict__ Wl,
                    float* __restrict__ out)
{
    extern __shared__ float sm[];
    const int tid = threadIdx.x;
    const int img = blockIdx.x;

    // -------------------- Phase 0: load 28x28 image, zero padded a2 --------
    {
        const float4* xg = (const float4*)(x + (size_t)img * 784);
        for (int i4 = tid; i4 < 196; i4 += 256) {
            float4 v = __ldg(&xg[i4]);
            int li = i4 * 4;
            int r = li / 28, c = li % 28;      // 28 % 4 == 0 -> same row
            float* p = &sm[SM_XS + r * 29 + c];
            p[0] = v.x; p[1] = v.y; p[2] = v.z; p[3] = v.w;
        }
        for (int i = tid; i < 2028; i += 256) sm[SM_A2P + i] = 0.0f;
    }
    __syncthreads();

    // -------------------- Phase 1: conv1 (valid 3x3, 32 ch, relu) ----------
    // task = (channel-pair, output row); sliding 3x3 window in registers.
    for (int task = tid; task < 416; task += 256) {
        int row = task % 26;
        int cp  = task / 26;
        int ch0 = cp * 2;
        float w0[9], w1[9];
#pragma unroll
        for (int k = 0; k < 9; k++) {
            w0[k] = c_w1[ch0 * 9 + k];
            w1[k] = c_w1[(ch0 + 1) * 9 + k];
        }
        float b0 = c_b1[ch0], b1v = c_b1[ch0 + 1];
        const float* xr = &sm[SM_XS + row * 29];
        float x00 = xr[0],  x01 = xr[1];
        float x10 = xr[29], x11 = xr[30];
        float x20 = xr[58], x21 = xr[59];
        float* o0 = &sm[SM_A1 + ch0 * 728 + row * 28];
        float* o1 = o0 + 728;
        for (int c = 0; c < 26; c++) {
            float x02 = xr[c + 2], x12 = xr[c + 31], x22 = xr[c + 60];
            float a = b0, b = b1v;
            a = fmaf(x00, w0[0], a); a = fmaf(x01, w0[1], a); a = fmaf(x02, w0[2], a);
            a = fmaf(x10, w0[3], a); a = fmaf(x11, w0[4], a); a = fmaf(x12, w0[5], a);
            a = fmaf(x20, w0[6], a); a = fmaf(x21, w0[7], a); a = fmaf(x22, w0[8], a);
            b = fmaf(x00, w1[0], b); b = fmaf(x01, w1[1], b); b = fmaf(x02, w1[2], b);
            b = fmaf(x10, w1[3], b); b = fmaf(x11, w1[4], b); b = fmaf(x12, w1[5], b);
            b = fmaf(x20, w1[6], b); b = fmaf(x21, w1[7], b); b = fmaf(x22, w1[8], b);
            o0[c] = fmaxf(a, 0.0f);
            o1[c] = fmaxf(b, 0.0f);
            x00 = x01; x01 = x02;
            x10 = x11; x11 = x12;
            x20 = x21; x21 = x22;
        }
    }
    __syncthreads();

    // -------------------- Phase 2: conv2 (valid 3x3, 32->3 ch) -------------
    // 192 threads: (output row, 3-px strip) x 3 oc accumulators.
    // Spare threads zero the SIFT cell accumulators meanwhile.
    if (tid >= 192) {
        for (int i = tid - 192; i < 384; i += 64) sm[SM_CELLS + i] = 0.0f;
        if (tid - 192 < 4) sm[SM_NORMS + (tid - 192)] = 0.0f;
    } else {
        int row = tid / 8;          // 0..23
        int xb  = (tid % 8) * 3;    // 0,3,...,21
        float acc[3][3];
#pragma unroll
        for (int oc = 0; oc < 3; oc++)
#pragma unroll
            for (int px = 0; px < 3; px++) acc[oc][px] = c_b2[oc];

        const float* ap0 = &sm[SM_A1 + row * 28 + xb];
        for (int ic = 0; ic < 32; ic++) {
            const float* ap = ap0 + ic * 728;
#pragma unroll
            for (int dy = 0; dy < 3; dy++) {
                float r0 = ap[dy * 28 + 0];
                float r1 = ap[dy * 28 + 1];
                float r2 = ap[dy * 28 + 2];
                float r3 = ap[dy * 28 + 3];
                float r4 = ap[dy * 28 + 4];
#pragma unroll
                for (int oc = 0; oc < 3; oc++) {
                    const float* wp = &c_w2[oc * 288 + ic * 9 + dy * 3];
                    float wa = wp[0], wb = wp[1], wc = wp[2];
                    acc[oc][0] = fmaf(r0, wa, acc[oc][0]);
                    acc[oc][1] = fmaf(r1, wa, acc[oc][1]);
                    acc[oc][2] = fmaf(r2, wa, acc[oc][2]);
                    acc[oc][0] = fmaf(r1, wb, acc[oc][0]);
                    acc[oc][1] = fmaf(r2, wb, acc[oc][1]);
                    acc[oc][2] = fmaf(r3, wb, acc[oc][2]);
                    acc[oc][0] = fmaf(r2, wc, acc[oc][0]);
                    acc[oc][1] = fmaf(r3, wc, acc[oc][1]);
                    acc[oc][2] = fmaf(r4, wc, acc[oc][2]);
                }
            }
        }
#pragma unroll
        for (int oc = 0; oc < 3; oc++)
#pragma unroll
            for (int px = 0; px < 3; px++)
                sm[SM_A2P + oc * 676 + (row + 1) * 26 + (xb + px + 1)] = acc[oc][px];
    }
    __syncthreads();

    // -------------------- Phase 3: SIFT per pixel ---------------------------
    // Sobel (zero-padded via a2p border), mag, 8-bin hard argmax (ties keep
    // all maximal bins, matching the JAX mask), accumulate into 4x4x8 cells.
    {
        const float CS[8] = { 0.92387953f,  0.38268343f, -0.38268343f, -0.92387953f,
                             -0.92387953f, -0.38268343f,  0.38268343f,  0.92387953f};
        const float SN[8] = { 0.38268343f,  0.92387953f,  0.92387953f,  0.38268343f,
                             -0.38268343f, -0.92387953f, -0.92387953f, -0.38268343f};
        for (int t = tid; t < 1728; t += 256) {
            int p   = t / 576;
            int pix = t % 576;
            int r = pix / 24, c = pix % 24;
            const float* ap = &sm[SM_A2P + p * 676 + (r + 1) * 26 + (c + 1)];
            float tl = ap[-27], tm = ap[-26], tr = ap[-25];
            float ml = ap[-1],                mr = ap[1];
            float bl2 = ap[25], bm = ap[26],  br = ap[27];
            float Ix = (tr - tl) + 2.0f * (mr - ml) + (br - bl2);
            float Iy = (bl2 - tl) + 2.0f * (bm - tm) + (br - tr);
            float mag = sqrtf(Ix * Ix + Iy * Iy + 1e-12f);
            float ck[8];
            float cmax = -1e30f;
#pragma unroll
            for (int k = 0; k < 8; k++) {
                ck[k] = CS[k] * Ix + SN[k] * Iy;
                cmax = fmaxf(cmax, ck[k]);
            }
            int fb = p * 128 + (r / 6) * 4 + (c / 6);
#pragma unroll
            for (int k = 0; k < 8; k++)
                if (ck[k] == cmax)
                    atomicAdd(&sm[SM_CELLS + fb + k * 16], mag);
        }
    }
    __syncthreads();

    // -------------------- Phase 4: L2 norm per patch + pow 0.9 -------------
    for (int i = tid; i < 384; i += 256) {
        float v = sm[SM_CELLS + i];
        atomicAdd(&sm[SM_NORMS + (i >> 7)], v * v);
    }
    __syncthreads();
    for (int i = tid; i < 384; i += 256) {
        float v = sm[SM_CELLS + i];
        float n = sqrtf(sm[SM_NORMS + (i >> 7)]);
        float f = v / (n + 1e-8f);
        sm[SM_CELLS + i] = powf(f + 1e-8f, 0.9f);
    }
    __syncthreads();

    // -------------------- Phase 5: 384 x 10 linear --------------------------
    {
        int w = tid >> 5, lane = tid & 31;
#pragma unroll
        for (int rep = 0; rep < 2; rep++) {
            int o = w + rep * 8;
            if (o < 10) {
                float s = 0.0f;
                const float* wrow = Wl + o * 384;
                for (int i = lane; i < 384; i += 32)
                    s = fmaf(sm[SM_CELLS + i], __ldg(&wrow[i]), s);
#pragma unroll
                for (int d = 16; d; d >>= 1)
                    s += __shfl_xor_sync(0xffffffffu, s, d);
                if (lane == 0) sm[SM_LOGITS + o] = s + c_bl[o];
            }
        }
    }
    __syncthreads();

    // -------------------- Phase 6: relu + softmax ---------------------------
    if (tid < 32) {
        float v = (tid < 10) ? fmaxf(sm[SM_LOGITS + tid], 0.0f) : -1e30f;
        float m = v;
#pragma unroll
        for (int d = 16; d; d >>= 1)
            m = fmaxf(m, __shfl_xor_sync(0xffffffffu, m, d));
        float e = (tid < 10) ? expf(v - m) : 0.0f;
        float ssum = e;
#pragma unroll
        for (int d = 16; d; d >>= 1)
            ssum += __shfl_xor_sync(0xffffffffu, ssum, d);
        if (tid < 10) out[(size_t)img * 10 + tid] = e / ssum;
    }
}

extern "C" void kernel_launch(void* const* d_in, const int* in_sizes, int n_in,
                              void* d_out, int out_size)
{
    const float* x  = (const float*)d_in[0];
    const float* W1 = (const float*)d_in[1];
    const float* b1 = (const float*)d_in[2];
    const float* W2 = (const float*)d_in[3];
    const float* b2 = (const float*)d_in[4];
    const float* Wl = (const float*)d_in[5];
    const float* bl = (const float*)d_in[6];

    int nimg = in_sizes[0] / 784;

    // Device-to-device copies into constant bank (graph-capturable memcpy nodes).
    cudaMemcpyToSymbolAsync(c_w1, W1, 288 * sizeof(float), 0, cudaMemcpyDeviceToDevice, 0);
    cudaMemcpyToSymbolAsync(c_b1, b1,  32 * sizeof(float), 0, cudaMemcpyDeviceToDevice, 0);
    cudaMemcpyToSymbolAsync(c_w2, W2, 864 * sizeof(float), 0, cudaMemcpyDeviceToDevice, 0);
    cudaMemcpyToSymbolAsync(c_b2, b2,   3 * sizeof(float), 0, cudaMemcpyDeviceToDevice, 0);
    cudaMemcpyToSymbolAsync(c_bl, bl,  10 * sizeof(float), 0, cudaMemcpyDeviceToDevice, 0);

    size_t smem = SM_FLOATS * sizeof(float);
    cudaFuncSetAttribute(fused_sift_net,
                         cudaFuncAttributeMaxDynamicSharedMemorySize, (int)smem);

    fused_sift_net<<<nimg, 256, smem>>>(x, Wl, (float*)d_out);
}

// round 2
// speedup vs baseline: 2.1725x; 2.1725x over previous
#include <cuda_runtime.h>

// Fused conv1(1->32) -> conv2(32->3) -> SIFT128 -> linear -> softmax.
// One CTA / image, 256 threads. a1 processed in 4 chunks of 8 channels so
// smem = 36.3KB -> 5 CTAs/SM. SIFT uses register histograms + shfl (no atomics).

__constant__ float c_w1[288];   // [32][3][3]
__constant__ float c_b1[32];
__constant__ float c_w2[864];   // [3][32][3][3]
__constant__ float c_b2[3];
__constant__ float c_bl[10];

// shared layout (floats)
#define SM_XS      0                   // 28 rows stride 29 -> 812
#define SM_A1      812                 // 8-ch chunk, stride 28/row, 728/ch -> 5824
#define SM_A2P     (SM_A1 + 5824)      // 3 ch padded 26x26 -> 2028
#define SM_CELLS   (SM_A2P + 2028)     // 384
#define SM_NORMS   (SM_CELLS + 384)    // 4
#define SM_LOGITS  (SM_NORMS + 4)      // 12
#define SM_FLOATS  (SM_LOGITS + 12)    // 9064 floats = 36256 B

__global__ __launch_bounds__(256, 5)
void fused_sift_net(const float* __restrict__ x,
                    const float* __restrict__ Wl,
                    float* __restrict__ out)
{
    extern __shared__ float sm[];
    const int tid = threadIdx.x;
    const int img = blockIdx.x;

    // ---------------- Phase 0: image load + zero padded a2 ----------------
    {
        const float4* xg = (const float4*)(x + (size_t)img * 784);
        for (int i4 = tid; i4 < 196; i4 += 256) {
            float4 v = __ldg(&xg[i4]);
            int li = i4 * 4;
            int r = li / 28, c = li % 28;
            float* p = &sm[SM_XS + r * 29 + c];
            p[0] = v.x; p[1] = v.y; p[2] = v.z; p[3] = v.w;
        }
        for (int i = tid; i < 2028; i += 256) sm[SM_A2P + i] = 0.0f;
    }

    // conv2 persistent accumulators (threads < 192)
    const int c2row = tid / 8;          // 0..23 (valid when tid<192)
    const int c2xb  = (tid % 8) * 3;
    float acc[3][3];
    if (tid < 192) {
#pragma unroll
        for (int oc = 0; oc < 3; oc++)
#pragma unroll
            for (int px = 0; px < 3; px++) acc[oc][px] = c_b2[oc];
    }

    // ---------------- Phases 1-2: 4 chunks of 8 channels -------------------
    for (int chunk = 0; chunk < 4; chunk++) {
        __syncthreads();   // prev conv2 done reading a1 (and phase0 on chunk 0)

        // conv1: 208 tasks = 4 ch-pairs x 26 rows x 2 half-rows (13 cols)
        if (tid < 208) {
            int pair = tid / 52;
            int tt   = tid % 52;
            int row  = tt >> 1;
            int half = tt & 1;
            int ch0  = chunk * 8 + pair * 2;
            float w0[9], w1[9];
#pragma unroll
            for (int k = 0; k < 9; k++) {
                w0[k] = c_w1[ch0 * 9 + k];
                w1[k] = c_w1[ch0 * 9 + 9 + k];
            }
            float b0 = c_b1[ch0], b1v = c_b1[ch0 + 1];
            const float* xr = &sm[SM_XS + row * 29 + half * 13];
            float x00 = xr[0],  x01 = xr[1];
            float x10 = xr[29], x11 = xr[30];
            float x20 = xr[58], x21 = xr[59];
            float* o0 = &sm[SM_A1 + (pair * 2) * 728 + row * 28 + half * 13];
            float* o1 = o0 + 728;
#pragma unroll
            for (int c = 0; c < 13; c++) {
                float x02 = xr[c + 2], x12 = xr[c + 31], x22 = xr[c + 60];
                float a = b0, b = b1v;
                a = fmaf(x00, w0[0], a); a = fmaf(x01, w0[1], a); a = fmaf(x02, w0[2], a);
                a = fmaf(x10, w0[3], a); a = fmaf(x11, w0[4], a); a = fmaf(x12, w0[5], a);
                a = fmaf(x20, w0[6], a); a = fmaf(x21, w0[7], a); a = fmaf(x22, w0[8], a);
                b = fmaf(x00, w1[0], b); b = fmaf(x01, w1[1], b); b = fmaf(x02, w1[2], b);
                b = fmaf(x10, w1[3], b); b = fmaf(x11, w1[4], b); b = fmaf(x12, w1[5], b);
                b = fmaf(x20, w1[6], b); b = fmaf(x21, w1[7], b); b = fmaf(x22, w1[8], b);
                o0[c] = fmaxf(a, 0.0f);
                o1[c] = fmaxf(b, 0.0f);
                x00 = x01; x01 = x02;
                x10 = x11; x11 = x12;
                x20 = x21; x21 = x22;
            }
        }
        __syncthreads();

        // conv2: accumulate this chunk's 8 input channels
        if (tid < 192) {
            const float* ap0 = &sm[SM_A1 + c2row * 28 + c2xb];
#pragma unroll
            for (int ic = 0; ic < 8; ic++) {
                const float* ap = ap0 + ic * 728;
                int icg9 = (chunk * 8 + ic) * 9;
#pragma unroll
                for (int dy = 0; dy < 3; dy++) {
                    float r0 = ap[dy * 28 + 0];
                    float r1 = ap[dy * 28 + 1];
                    float r2 = ap[dy * 28 + 2];
                    float r3 = ap[dy * 28 + 3];
                    float r4 = ap[dy * 28 + 4];
#pragma unroll
                    for (int oc = 0; oc < 3; oc++) {
                        const float* wp = &c_w2[oc * 288 + icg9 + dy * 3];
                        float wa = wp[0], wb = wp[1], wc = wp[2];
                        acc[oc][0] = fmaf(r0, wa, acc[oc][0]);
                        acc[oc][1] = fmaf(r1, wa, acc[oc][1]);
                        acc[oc][2] = fmaf(r2, wa, acc[oc][2]);
                        acc[oc][0] = fmaf(r1, wb, acc[oc][0]);
                        acc[oc][1] = fmaf(r2, wb, acc[oc][1]);
                        acc[oc][2] = fmaf(r3, wb, acc[oc][2]);
                        acc[oc][0] = fmaf(r2, wc, acc[oc][0]);
                        acc[oc][1] = fmaf(r3, wc, acc[oc][1]);
                        acc[oc][2] = fmaf(r4, wc, acc[oc][2]);
                    }
                }
            }
        }
    }

    // write conv2 outputs into padded tile
    if (tid < 192) {
#pragma unroll
        for (int oc = 0; oc < 3; oc++)
#pragma unroll
            for (int px = 0; px < 3; px++)
                sm[SM_A2P + oc * 676 + (c2row + 1) * 26 + (c2xb + px + 1)] = acc[oc][px];
    }
    __syncthreads();

    // ---------------- Phase 3: SIFT, register histograms, no atomics ------
    if (tid < 192) {
        const float CS[8] = { 0.92387953f,  0.38268343f, -0.38268343f, -0.92387953f,
                             -0.92387953f, -0.38268343f,  0.38268343f,  0.92387953f};
        const float SN[8] = { 0.38268343f,  0.92387953f,  0.92387953f,  0.38268343f,
                             -0.38268343f, -0.92387953f, -0.92387953f, -0.38268343f};
        int p    = tid / 64;
        int rem  = tid % 64;
        int cell = rem >> 2;        // 0..15
        int quad = rem & 3;         // 0..3 (== lane & 3)
        int r0 = (cell >> 2) * 6 + (quad >> 1) * 3;
        int c0 = (cell & 3) * 6 + (quad & 1) * 3;
        const float* ap = &sm[SM_A2P + p * 676 + r0 * 26 + c0];
        float pt[5][5];
#pragma unroll
        for (int i = 0; i < 5; i++)
#pragma unroll
            for (int j = 0; j < 5; j++) pt[i][j] = ap[i * 26 + j];

        float hist[8] = {0,0,0,0,0,0,0,0};
#pragma unroll
        for (int i = 0; i < 3; i++) {
#pragma unroll
            for (int j = 0; j < 3; j++) {
                float Ix = (pt[i][j+2] - pt[i][j])
                         + 2.0f * (pt[i+1][j+2] - pt[i+1][j])
                         + (pt[i+2][j+2] - pt[i+2][j]);
                float Iy = (pt[i+2][j] - pt[i][j])
                         + 2.0f * (pt[i+2][j+1] - pt[i][j+1])
                         + (pt[i+2][j+2] - pt[i][j+2]);
                float mag = sqrtf(Ix * Ix + Iy * Iy + 1e-12f);
                float ck[8];
                float cmax = -1e30f;
#pragma unroll
                for (int k = 0; k < 8; k++) {
                    ck[k] = CS[k] * Ix + SN[k] * Iy;
                    cmax = fmaxf(cmax, ck[k]);
                }
#pragma unroll
                for (int k = 0; k < 8; k++)
                    hist[k] += (ck[k] == cmax) ? mag : 0.0f;
            }
        }
        // reduce the 4 quadrant threads (lanes 4k..4k+3 of the same warp)
#pragma unroll
        for (int k = 0; k < 8; k++) {
            float v = hist[k];
            v += __shfl_xor_sync(0xffffffffu, v, 1);
            v += __shfl_xor_sync(0xffffffffu, v, 2);
            if (quad == 0)
                sm[SM_CELLS + p * 128 + k * 16 + cell] = v;
        }
    }
    __syncthreads();

    // ---------------- Phase 4: norms (warp reduce) + pow 0.9 ---------------
    if (tid < 96) {
        int w = tid >> 5, lane = tid & 31;
        const float* cp = &sm[SM_CELLS + w * 128];
        float s = 0.0f;
#pragma unroll
        for (int j = 0; j < 4; j++) {
            float v = cp[lane + 32 * j];
            s = fmaf(v, v, s);
        }
#pragma unroll
        for (int d = 16; d; d >>= 1)
            s += __shfl_xor_sync(0xffffffffu, s, d);
        if (lane == 0) sm[SM_NORMS + w] = sqrtf(s);
    }
    __syncthreads();
    {
        int i = tid;
        if (i < 384) {
            float v = sm[SM_CELLS + i];
            float f = v / (sm[SM_NORMS + (i >> 7)] + 1e-8f);
            sm[SM_CELLS + i] = powf(f + 1e-8f, 0.9f);
        }
        i = tid + 256;
        if (i < 384) {
            float v = sm[SM_CELLS + i];
            float f = v / (sm[SM_NORMS + (i >> 7)] + 1e-8f);
            sm[SM_CELLS + i] = powf(f + 1e-8f, 0.9f);
        }
    }
    __syncthreads();

    // ---------------- Phase 5: 384x10 linear --------------------------------
    {
        int w = tid >> 5, lane = tid & 31;
#pragma unroll
        for (int rep = 0; rep < 2; rep++) {
            int o = w + rep * 8;
            if (o < 10) {
                float s = 0.0f;
                const float* wrow = Wl + o * 384;
                for (int i = lane; i < 384; i += 32)
                    s = fmaf(sm[SM_CELLS + i], __ldg(&wrow[i]), s);
#pragma unroll
                for (int d = 16; d; d >>= 1)
                    s += __shfl_xor_sync(0xffffffffu, s, d);
                if (lane == 0) sm[SM_LOGITS + o] = s + c_bl[o];
            }
        }
    }
    __syncthreads();

    // ---------------- Phase 6: relu + softmax -------------------------------
    if (tid < 32) {
        float v = (tid < 10) ? fmaxf(sm[SM_LOGITS + tid], 0.0f) : -1e30f;
        float m = v;
#pragma unroll
        for (int d = 16; d; d >>= 1)
            m = fmaxf(m, __shfl_xor_sync(0xffffffffu, m, d));
        float e = (tid < 10) ? expf(v - m) : 0.0f;
        float ssum = e;
#pragma unroll
        for (int d = 16; d; d >>= 1)
            ssum += __shfl_xor_sync(0xffffffffu, ssum, d);
        if (tid < 10) out[(size_t)img * 10 + tid] = e / ssum;
    }
}

extern "C" void kernel_launch(void* const* d_in, const int* in_sizes, int n_in,
                              void* d_out, int out_size)
{
    const float* x  = (const float*)d_in[0];
    const float* W1 = (const float*)d_in[1];
    const float* b1 = (const float*)d_in[2];
    const float* W2 = (const float*)d_in[3];
    const float* b2 = (const float*)d_in[4];
    const float* Wl = (const float*)d_in[5];
    const float* bl = (const float*)d_in[6];

    int nimg = in_sizes[0] / 784;

    cudaMemcpyToSymbolAsync(c_w1, W1, 288 * sizeof(float), 0, cudaMemcpyDeviceToDevice, 0);
    cudaMemcpyToSymbolAsync(c_b1, b1,  32 * sizeof(float), 0, cudaMemcpyDeviceToDevice, 0);
    cudaMemcpyToSymbolAsync(c_w2, W2, 864 * sizeof(float), 0, cudaMemcpyDeviceToDevice, 0);
    cudaMemcpyToSymbolAsync(c_b2, b2,   3 * sizeof(float), 0, cudaMemcpyDeviceToDevice, 0);
    cudaMemcpyToSymbolAsync(c_bl, bl,  10 * sizeof(float), 0, cudaMemcpyDeviceToDevice, 0);

    size_t smem = SM_FLOATS * sizeof(float);
    cudaFuncSetAttribute(fused_sift_net,
                         cudaFuncAttributeMaxDynamicSharedMemorySize, (int)smem);

    fused_sift_net<<<nimg, 256, smem>>>(x, Wl, (float*)d_out);
}